// round 2
// baseline (speedup 1.0000x reference)
#include <cuda_runtime.h>

#define USER_NUM    100000
#define ITEM_NUM    50000
#define CONCEPT_NUM 2000
#define NTOT        150000      // USER_NUM + ITEM_NUM
#define EMB         64
#define EPS_F       0.1f
#define NNZ_ADJ     2400000
#define NNZ_PRE     16000
#define NNZ_IC      250000
#define N_LAYERS    3

// ---- scratch (device globals; no dynamic allocation allowed) ----
__device__ __align__(16) float g_ego[NTOT * EMB];        // layer input embeddings
__device__ __align__(16) float g_y[NTOT * EMB];          // SPMM accumulator
__device__ __align__(16) float g_ca[CONCEPT_NUM * EMB];  // concept ping
__device__ __align__(16) float g_cb[CONCEPT_NUM * EMB];  // concept pong

// no-return vectorized global reduction (PTX ISA 8.1+, sm_90+)
__device__ __forceinline__ void red_add_v4(float* addr, float a, float b, float c, float d) {
    asm volatile("red.global.add.v4.f32 [%0], {%1, %2, %3, %4};"
                 :: "l"(addr), "f"(a), "f"(b), "f"(c), "f"(d)
                 : "memory");
}

// ---- init: ego = concat(user, item); y = 0; out(acc) = 0; ca = concept ----
__global__ void init_kernel(const float* __restrict__ ue,
                            const float* __restrict__ ie,
                            const float* __restrict__ ce,
                            float* __restrict__ out) {
    const int tot4  = NTOT * EMB / 4;
    const int user4 = USER_NUM * EMB / 4;
    const int c4    = CONCEPT_NUM * EMB / 4;
    for (int i = blockIdx.x * blockDim.x + threadIdx.x;
         i < tot4; i += gridDim.x * blockDim.x) {
        float4 v;
        if (i < user4) v = ((const float4*)ue)[i];
        else           v = ((const float4*)ie)[i - user4];
        ((float4*)g_ego)[i] = v;
        ((float4*)g_y)[i]   = make_float4(0.f, 0.f, 0.f, 0.f);
        ((float4*)out)[i]   = make_float4(0.f, 0.f, 0.f, 0.f);
        if (i < c4) ((float4*)g_ca)[i] = ((const float4*)ce)[i];
    }
}

// ---- adj SPMM: y[r] += v * ego[c]; 16 threads per edge, float4 each ----
__global__ void spmm_adj_kernel(const int* __restrict__ rows,
                                const int* __restrict__ cols,
                                const float* __restrict__ vals) {
    int t0   = blockIdx.x * blockDim.x + threadIdx.x;
    int lane = t0 & 15;
    for (int t = t0; t < NNZ_ADJ * 16; t += gridDim.x * blockDim.x) {
        int   e = t >> 4;
        int   r = __ldg(&rows[e]);
        int   c = __ldg(&cols[e]);
        float v = __ldg(&vals[e]);
        float4 x = ((const float4*)g_ego)[c * 16 + lane];
        red_add_v4(&g_y[r * 64 + lane * 4], v * x.x, v * x.y, v * x.z, v * x.w);
    }
}

// ---- concept copy: dst = src (parity selects ping/pong) ----
__global__ void copy_c_kernel(int parity) {
    const float4* src = parity ? (const float4*)g_cb : (const float4*)g_ca;
    float4*       dst = parity ? (float4*)g_ca       : (float4*)g_cb;
    const int c4 = CONCEPT_NUM * EMB / 4;
    for (int i = blockIdx.x * blockDim.x + threadIdx.x;
         i < c4; i += gridDim.x * blockDim.x) {
        dst[i] = src[i];
    }
}

// ---- pre SPMM: c_dst[r] += v * c_src[c] ----
__global__ void spmm_pre_kernel(const int* __restrict__ rows,
                                const int* __restrict__ cols,
                                const float* __restrict__ vals,
                                int parity) {
    const float* src = parity ? g_cb : g_ca;
    float*       dst = parity ? g_ca : g_cb;
    int t0   = blockIdx.x * blockDim.x + threadIdx.x;
    int lane = t0 & 15;
    for (int t = t0; t < NNZ_PRE * 16; t += gridDim.x * blockDim.x) {
        int   e = t >> 4;
        int   r = __ldg(&rows[e]);
        int   c = __ldg(&cols[e]);
        float v = __ldg(&vals[e]);
        float4 x = ((const float4*)src)[c * 16 + lane];
        red_add_v4(&dst[r * 64 + lane * 4], v * x.x, v * x.y, v * x.z, v * x.w);
    }
}

// ---- ic SPMM into item rows of y: y[USER_NUM + r] += 0.1 * v * c_new[c] ----
__global__ void spmm_ic_kernel(const int* __restrict__ rows,
                               const int* __restrict__ cols,
                               const float* __restrict__ vals,
                               int parity) {
    const float* cn = parity ? g_ca : g_cb;   // this layer's updated concepts
    int t0   = blockIdx.x * blockDim.x + threadIdx.x;
    int lane = t0 & 15;
    for (int t = t0; t < NNZ_IC * 16; t += gridDim.x * blockDim.x) {
        int   e = t >> 4;
        int   r = __ldg(&rows[e]);
        int   c = __ldg(&cols[e]);
        float v = 0.1f * __ldg(&vals[e]);
        float4 x = ((const float4*)cn)[c * 16 + lane];
        red_add_v4(&g_y[(USER_NUM + r) * 64 + lane * 4],
                   v * x.x, v * x.y, v * x.z, v * x.w);
    }
}

__device__ __forceinline__ float signf_(float x) {
    return (x > 0.f) ? 1.f : ((x < 0.f) ? -1.f : 0.f);
}

// ---- perturb + accumulate + re-zero y:
//   e = y[row]; e += sign(e) * (nk/||nk||) * EPS
//   ego[row] = e; out[row] = (out[row] + e) * scale; y[row] = 0
__global__ void perturb_kernel(const float* __restrict__ nk,
                               float* __restrict__ out,
                               float scale) {
    int t0   = blockIdx.x * blockDim.x + threadIdx.x;
    int lane = t0 & 15;
    for (int t = t0; t < NTOT * 16; t += gridDim.x * blockDim.x) {
        int row  = t >> 4;
        int idx4 = row * 16 + lane;

        float4 n = ((const float4*)nk)[idx4];
        float ss = n.x * n.x + n.y * n.y + n.z * n.z + n.w * n.w;
        // reduce sum-of-squares across the 16-lane group (xor stays in-group)
        ss += __shfl_xor_sync(0xffffffffu, ss, 1);
        ss += __shfl_xor_sync(0xffffffffu, ss, 2);
        ss += __shfl_xor_sync(0xffffffffu, ss, 4);
        ss += __shfl_xor_sync(0xffffffffu, ss, 8);
        float inv = EPS_F / fmaxf(sqrtf(ss), 1e-12f);

        float4 e = ((const float4*)g_y)[idx4];
        e.x += signf_(e.x) * n.x * inv;
        e.y += signf_(e.y) * n.y * inv;
        e.z += signf_(e.z) * n.z * inv;
        e.w += signf_(e.w) * n.w * inv;

        ((float4*)g_ego)[idx4] = e;
        ((float4*)g_y)[idx4]   = make_float4(0.f, 0.f, 0.f, 0.f);

        float4 a = ((float4*)out)[idx4];
        a.x = (a.x + e.x) * scale;
        a.y = (a.y + e.y) * scale;
        a.z = (a.z + e.z) * scale;
        a.w = (a.w + e.w) * scale;
        ((float4*)out)[idx4] = a;
    }
}

extern "C" void kernel_launch(void* const* d_in, const int* in_sizes, int n_in,
                              void* d_out, int out_size) {
    const float* user_emb    = (const float*)d_in[0];
    const float* item_emb    = (const float*)d_in[1];
    const float* concept_emb = (const float*)d_in[2];
    const int*   adj_rows    = (const int*)d_in[3];
    const int*   adj_cols    = (const int*)d_in[4];
    const float* adj_vals    = (const float*)d_in[5];
    const int*   pre_rows    = (const int*)d_in[6];
    const int*   pre_cols    = (const int*)d_in[7];
    const float* pre_vals    = (const float*)d_in[8];
    const int*   ic_rows     = (const int*)d_in[9];
    const int*   ic_cols     = (const int*)d_in[10];
    const float* ic_vals     = (const float*)d_in[11];
    const float* noise       = (const float*)d_in[12];
    float* out = (float*)d_out;

    const int TPB = 256;
    const int init_blocks = (NTOT * EMB / 4 + TPB - 1) / TPB;
    const int adj_blocks  = (NNZ_ADJ * 16 + TPB - 1) / TPB;
    const int cc_blocks   = (CONCEPT_NUM * EMB / 4 + TPB - 1) / TPB;
    const int pre_blocks  = (NNZ_PRE * 16 + TPB - 1) / TPB;
    const int ic_blocks   = (NNZ_IC * 16 + TPB - 1) / TPB;
    const int pert_blocks = (NTOT * 16 + TPB - 1) / TPB;

    init_kernel<<<init_blocks, TPB>>>(user_emb, item_emb, concept_emb, out);

    for (int k = 0; k < N_LAYERS; ++k) {
        int parity = k & 1;
        spmm_adj_kernel<<<adj_blocks, TPB>>>(adj_rows, adj_cols, adj_vals);
        copy_c_kernel<<<cc_blocks, TPB>>>(parity);
        spmm_pre_kernel<<<pre_blocks, TPB>>>(pre_rows, pre_cols, pre_vals, parity);
        spmm_ic_kernel<<<ic_blocks, TPB>>>(ic_rows, ic_cols, ic_vals, parity);
        float scale = (k == N_LAYERS - 1) ? (1.f / (float)N_LAYERS) : 1.f;
        perturb_kernel<<<pert_blocks, TPB>>>(noise + (size_t)k * NTOT * EMB, out, scale);
    }
}

// round 3
// speedup vs baseline: 1.6143x; 1.6143x over previous
#include <cuda_runtime.h>

#define USER_NUM    100000
#define ITEM_NUM    50000
#define CONCEPT_NUM 2000
#define NTOT        150000      // USER_NUM + ITEM_NUM
#define EMB         64
#define EPS_F       0.1f
#define NNZ_ADJ     2400000
#define NNZ_PRE     16000
#define NNZ_IC      250000
#define N_LAYERS    3
#define CAP_ADJ     64          // Poisson(16) over 150K rows: overflow prob ~1e-20
#define CAP_IC      32          // Poisson(5)  over 50K rows

// ---- scratch (device globals; no dynamic allocation allowed) ----
__device__ __align__(16) float g_ego_a[NTOT * EMB];
__device__ __align__(16) float g_ego_b[NTOT * EMB];
__device__ __align__(16) float g_ca[CONCEPT_NUM * EMB];   // concept ping
__device__ __align__(16) float g_cb[CONCEPT_NUM * EMB];   // concept pong
__device__ int  g_adj_cnt[NTOT];
__device__ int  g_ic_cnt[ITEM_NUM];
__device__ __align__(8) int2 g_adj_ell[(size_t)NTOT * CAP_ADJ];     // (col, val bits)
__device__ __align__(8) int2 g_ic_ell[(size_t)ITEM_NUM * CAP_IC];   // (col, 0.1*val bits)

// no-return vectorized global reduction (sm_90+)
__device__ __forceinline__ void red_add_v4(float* addr, float a, float b, float c, float d) {
    asm volatile("red.global.add.v4.f32 [%0], {%1, %2, %3, %4};"
                 :: "l"(addr), "f"(a), "f"(b), "f"(c), "f"(d)
                 : "memory");
}

__device__ __forceinline__ float signf_(float x) {
    return (x > 0.f) ? 1.f : ((x < 0.f) ? -1.f : 0.f);
}

// ---- zero the ELL counters (must run every launch: graph is replayed) ----
__global__ void zero_cnt_kernel() {
    int i = blockIdx.x * blockDim.x + threadIdx.x;
    if (i < NTOT) g_adj_cnt[i] = 0;
    if (i < ITEM_NUM) g_ic_cnt[i] = 0;
}

// ---- init: ego_a = concat(user, item); ca = concept ----
__global__ void init_kernel(const float* __restrict__ ue,
                            const float* __restrict__ ie,
                            const float* __restrict__ ce) {
    const int tot4  = NTOT * EMB / 4;
    const int user4 = USER_NUM * EMB / 4;
    const int c4    = CONCEPT_NUM * EMB / 4;
    for (int i = blockIdx.x * blockDim.x + threadIdx.x;
         i < tot4; i += gridDim.x * blockDim.x) {
        float4 v;
        if (i < user4) v = ((const float4*)ue)[i];
        else           v = ((const float4*)ie)[i - user4];
        ((float4*)g_ego_a)[i] = v;
        if (i < c4) ((float4*)g_ca)[i] = ((const float4*)ce)[i];
    }
}

// ---- build adj ELL: bucket edges by destination row ----
__global__ void build_adj_kernel(const int* __restrict__ rows,
                                 const int* __restrict__ cols,
                                 const float* __restrict__ vals) {
    for (int e = blockIdx.x * blockDim.x + threadIdx.x;
         e < NNZ_ADJ; e += gridDim.x * blockDim.x) {
        int r = rows[e];
        int pos = atomicAdd(&g_adj_cnt[r], 1);
        if (pos < CAP_ADJ)
            g_adj_ell[(size_t)r * CAP_ADJ + pos] =
                make_int2(cols[e], __float_as_int(vals[e]));
    }
}

// ---- build ic ELL (0.1 prefolded into value) ----
__global__ void build_ic_kernel(const int* __restrict__ rows,
                                const int* __restrict__ cols,
                                const float* __restrict__ vals) {
    for (int e = blockIdx.x * blockDim.x + threadIdx.x;
         e < NNZ_IC; e += gridDim.x * blockDim.x) {
        int r = rows[e];
        int pos = atomicAdd(&g_ic_cnt[r], 1);
        if (pos < CAP_IC)
            g_ic_ell[(size_t)r * CAP_IC + pos] =
                make_int2(cols[e], __float_as_int(0.1f * vals[e]));
    }
}

// ---- concept copy: dst = src ----
__global__ void copy_c_kernel(int parity) {
    const float4* src = parity ? (const float4*)g_cb : (const float4*)g_ca;
    float4*       dst = parity ? (float4*)g_ca       : (float4*)g_cb;
    const int c4 = CONCEPT_NUM * EMB / 4;
    int i = blockIdx.x * blockDim.x + threadIdx.x;
    if (i < c4) dst[i] = src[i];
}

// ---- pre SPMM (atomic; tiny): c_dst[r] += v * c_src[c] ----
__global__ void spmm_pre_kernel(const int* __restrict__ rows,
                                const int* __restrict__ cols,
                                const float* __restrict__ vals,
                                int parity) {
    const float* src = parity ? g_cb : g_ca;
    float*       dst = parity ? g_ca : g_cb;
    int t = blockIdx.x * blockDim.x + threadIdx.x;
    if (t >= NNZ_PRE * 16) return;
    int e    = t >> 4;
    int lane = t & 15;
    int   r = __ldg(&rows[e]);
    int   c = __ldg(&cols[e]);
    float v = __ldg(&vals[e]);
    float4 x = ((const float4*)src)[c * 16 + lane];
    red_add_v4(&dst[r * 64 + lane * 4], v * x.x, v * x.y, v * x.z, v * x.w);
}

// ---- fused layer: adj-SPMM (+ic for item rows) + perturb + accumulate ----
// mode: 0 = first layer (out = e), 1 = middle (out += e), 2 = last (out = (out+e)/3)
__global__ void layer_kernel(const float* __restrict__ ego_src,
                             float* __restrict__ ego_dst,
                             const float* __restrict__ cn,   // this layer's updated concepts
                             const float* __restrict__ nk,
                             float* __restrict__ out,
                             int mode) {
    int t0   = blockIdx.x * blockDim.x + threadIdx.x;
    int lane = threadIdx.x & 15;
    for (int t = t0; t < NTOT * 16; t += gridDim.x * blockDim.x) {
        int row  = t >> 4;
        int idx4 = row * 16 + lane;

        float4 acc = make_float4(0.f, 0.f, 0.f, 0.f);
        int n = g_adj_cnt[row];
        const int2* ell = &g_adj_ell[(size_t)row * CAP_ADJ];
        for (int i = 0; i < n; ++i) {
            int2  ed = ell[i];                 // broadcast across 16 lanes
            float v  = __int_as_float(ed.y);
            float4 x = ((const float4*)ego_src)[ed.x * 16 + lane];
            acc.x += v * x.x; acc.y += v * x.y;
            acc.z += v * x.z; acc.w += v * x.w;
        }
        if (row >= USER_NUM) {
            int ir = row - USER_NUM;
            int m = g_ic_cnt[ir];
            const int2* ell2 = &g_ic_ell[(size_t)ir * CAP_IC];
            for (int i = 0; i < m; ++i) {
                int2  ed = ell2[i];
                float v  = __int_as_float(ed.y);   // 0.1 prefolded
                float4 x = ((const float4*)cn)[ed.x * 16 + lane];
                acc.x += v * x.x; acc.y += v * x.y;
                acc.z += v * x.z; acc.w += v * x.w;
            }
        }

        // SimGCL perturbation: e += sign(e) * (nk/||nk||) * eps
        float4 nv = ((const float4*)nk)[idx4];
        float ss = nv.x * nv.x + nv.y * nv.y + nv.z * nv.z + nv.w * nv.w;
        ss += __shfl_xor_sync(0xffffffffu, ss, 1);
        ss += __shfl_xor_sync(0xffffffffu, ss, 2);
        ss += __shfl_xor_sync(0xffffffffu, ss, 4);
        ss += __shfl_xor_sync(0xffffffffu, ss, 8);
        float inv = EPS_F / fmaxf(sqrtf(ss), 1e-12f);

        acc.x += signf_(acc.x) * nv.x * inv;
        acc.y += signf_(acc.y) * nv.y * inv;
        acc.z += signf_(acc.z) * nv.z * inv;
        acc.w += signf_(acc.w) * nv.w * inv;

        ((float4*)ego_dst)[idx4] = acc;

        if (mode == 0) {
            ((float4*)out)[idx4] = acc;
        } else {
            float4 a = ((float4*)out)[idx4];
            a.x += acc.x; a.y += acc.y; a.z += acc.z; a.w += acc.w;
            if (mode == 2) {
                const float s = 1.f / (float)N_LAYERS;
                a.x *= s; a.y *= s; a.z *= s; a.w *= s;
            }
            ((float4*)out)[idx4] = a;
        }
    }
}

extern "C" void kernel_launch(void* const* d_in, const int* in_sizes, int n_in,
                              void* d_out, int out_size) {
    const float* user_emb    = (const float*)d_in[0];
    const float* item_emb    = (const float*)d_in[1];
    const float* concept_emb = (const float*)d_in[2];
    const int*   adj_rows    = (const int*)d_in[3];
    const int*   adj_cols    = (const int*)d_in[4];
    const float* adj_vals    = (const float*)d_in[5];
    const int*   pre_rows    = (const int*)d_in[6];
    const int*   pre_cols    = (const int*)d_in[7];
    const float* pre_vals    = (const float*)d_in[8];
    const int*   ic_rows     = (const int*)d_in[9];
    const int*   ic_cols     = (const int*)d_in[10];
    const float* ic_vals     = (const float*)d_in[11];
    const float* noise       = (const float*)d_in[12];
    float* out = (float*)d_out;

    const int TPB = 256;
    const int zc_blocks    = (NTOT + TPB - 1) / TPB;
    const int init_blocks  = (NTOT * EMB / 4 + TPB - 1) / TPB;
    const int badj_blocks  = (NNZ_ADJ + TPB - 1) / TPB;
    const int bic_blocks   = (NNZ_IC + TPB - 1) / TPB;
    const int cc_blocks    = (CONCEPT_NUM * EMB / 4 + TPB - 1) / TPB;
    const int pre_blocks   = (NNZ_PRE * 16 + TPB - 1) / TPB;
    const int layer_blocks = (NTOT * 16 + TPB - 1) / TPB;

    zero_cnt_kernel<<<zc_blocks, TPB>>>();
    init_kernel<<<init_blocks, TPB>>>(user_emb, item_emb, concept_emb);
    build_adj_kernel<<<badj_blocks, TPB>>>(adj_rows, adj_cols, adj_vals);
    build_ic_kernel<<<bic_blocks, TPB>>>(ic_rows, ic_cols, ic_vals);

    // ego ping-pong: layer k reads src, writes dst
    float* ego_bufs[2];
    cudaGetSymbolAddress((void**)&ego_bufs[0], g_ego_a);
    cudaGetSymbolAddress((void**)&ego_bufs[1], g_ego_b);
    float* c_bufs[2];
    cudaGetSymbolAddress((void**)&c_bufs[0], g_ca);
    cudaGetSymbolAddress((void**)&c_bufs[1], g_cb);

    for (int k = 0; k < N_LAYERS; ++k) {
        int parity = k & 1;                    // concept dst: parity? g_ca : g_cb
        copy_c_kernel<<<cc_blocks, TPB>>>(parity);
        spmm_pre_kernel<<<pre_blocks, TPB>>>(pre_rows, pre_cols, pre_vals, parity);
        const float* cn = parity ? c_bufs[0] : c_bufs[1];
        const float* esrc = ego_bufs[k & 1];
        float*       edst = ego_bufs[(k + 1) & 1];
        int mode = (k == 0) ? 0 : (k == N_LAYERS - 1 ? 2 : 1);
        layer_kernel<<<layer_blocks, TPB>>>(esrc, edst, cn,
                                            noise + (size_t)k * NTOT * EMB,
                                            out, mode);
    }
}

// round 5
// speedup vs baseline: 1.7833x; 1.1047x over previous
#include <cuda_runtime.h>

#define USER_NUM    100000
#define ITEM_NUM    50000
#define CONCEPT_NUM 2000
#define NTOT        150000      // USER_NUM + ITEM_NUM
#define EMB         64
#define EPS_F       0.1f
#define NNZ_ADJ     2400000
#define NNZ_PRE     16000
#define NNZ_IC      250000
#define N_LAYERS    3
#define CAP_ADJ     64          // Poisson(16) over 150K rows: overflow prob ~1e-20
#define CAP_IC      32          // Poisson(5)  over 50K rows

// ---- scratch (device globals; no dynamic allocation allowed) ----
__device__ __align__(256) float g_ego_a[NTOT * EMB];
__device__ __align__(256) float g_ego_b[NTOT * EMB];
__device__ __align__(256) float g_ca[CONCEPT_NUM * EMB];   // concept ping
__device__ __align__(256) float g_cb[CONCEPT_NUM * EMB];   // concept pong
__device__ int  g_adj_cnt[NTOT];
__device__ int  g_ic_cnt[ITEM_NUM];
__device__ __align__(16) int2 g_adj_ell[(size_t)NTOT * CAP_ADJ];     // (col, val bits)
__device__ __align__(16) int2 g_ic_ell[(size_t)ITEM_NUM * CAP_IC];   // (col, 0.1*val bits)

// no-return vectorized global reduction (sm_90+)
__device__ __forceinline__ void red_add_v4(float* addr, float a, float b, float c, float d) {
    asm volatile("red.global.add.v4.f32 [%0], {%1, %2, %3, %4};"
                 :: "l"(addr), "f"(a), "f"(b), "f"(c), "f"(d)
                 : "memory");
}

__device__ __forceinline__ float signf_(float x) {
    return (x > 0.f) ? 1.f : ((x < 0.f) ? -1.f : 0.f);
}

// ---- zero the ELL counters (must run every launch: graph is replayed) ----
__global__ void zero_cnt_kernel() {
    int i = blockIdx.x * blockDim.x + threadIdx.x;
    if (i < NTOT) g_adj_cnt[i] = 0;
    if (i < ITEM_NUM) g_ic_cnt[i] = 0;
}

// ---- init: ego_a = concat(user, item); ca = concept ----
__global__ void init_kernel(const float* __restrict__ ue,
                            const float* __restrict__ ie,
                            const float* __restrict__ ce) {
    const int tot4  = NTOT * EMB / 4;
    const int user4 = USER_NUM * EMB / 4;
    const int c4    = CONCEPT_NUM * EMB / 4;
    for (int i = blockIdx.x * blockDim.x + threadIdx.x;
         i < tot4; i += gridDim.x * blockDim.x) {
        float4 v;
        if (i < user4) v = ((const float4*)ue)[i];
        else           v = ((const float4*)ie)[i - user4];
        ((float4*)g_ego_a)[i] = v;
        if (i < c4) ((float4*)g_ca)[i] = ((const float4*)ce)[i];
    }
}

// ---- build adj ELL: bucket edges by destination row ----
__global__ void build_adj_kernel(const int* __restrict__ rows,
                                 const int* __restrict__ cols,
                                 const float* __restrict__ vals) {
    for (int e = blockIdx.x * blockDim.x + threadIdx.x;
         e < NNZ_ADJ; e += gridDim.x * blockDim.x) {
        int r = rows[e];
        int pos = atomicAdd(&g_adj_cnt[r], 1);
        if (pos < CAP_ADJ)
            g_adj_ell[(size_t)r * CAP_ADJ + pos] =
                make_int2(cols[e], __float_as_int(vals[e]));
    }
}

// ---- build ic ELL (0.1 prefolded into value) ----
__global__ void build_ic_kernel(const int* __restrict__ rows,
                                const int* __restrict__ cols,
                                const float* __restrict__ vals) {
    for (int e = blockIdx.x * blockDim.x + threadIdx.x;
         e < NNZ_IC; e += gridDim.x * blockDim.x) {
        int r = rows[e];
        int pos = atomicAdd(&g_ic_cnt[r], 1);
        if (pos < CAP_IC)
            g_ic_ell[(size_t)r * CAP_IC + pos] =
                make_int2(cols[e], __float_as_int(0.1f * vals[e]));
    }
}

// ---- pad each ELL row up to a multiple of 4 with zero-valued edges ----
// (col 0 is always a valid index; v=0 contributes exactly 0)
__global__ void pad_ell_kernel() {
    int t = blockIdx.x * blockDim.x + threadIdx.x;
    if (t < NTOT) {
        int n  = min(g_adj_cnt[t], CAP_ADJ);
        int n4 = (n + 3) & ~3;
        int2* ell = &g_adj_ell[(size_t)t * CAP_ADJ];
        for (int j = n; j < n4; ++j) ell[j] = make_int2(0, 0);
    } else if (t < NTOT + ITEM_NUM) {
        int r  = t - NTOT;
        int n  = min(g_ic_cnt[r], CAP_IC);
        int n4 = (n + 3) & ~3;
        int2* ell = &g_ic_ell[(size_t)r * CAP_IC];
        for (int j = n; j < n4; ++j) ell[j] = make_int2(0, 0);
    }
}

// ---- concept copy: dst = src ----
__global__ void copy_c_kernel(int parity) {
    const float4* src = parity ? (const float4*)g_cb : (const float4*)g_ca;
    float4*       dst = parity ? (float4*)g_ca       : (float4*)g_cb;
    const int c4 = CONCEPT_NUM * EMB / 4;
    int i = blockIdx.x * blockDim.x + threadIdx.x;
    if (i < c4) dst[i] = src[i];
}

// ---- pre SPMM (atomic; tiny): c_dst[r] += v * c_src[c] ----
__global__ void spmm_pre_kernel(const int* __restrict__ rows,
                                const int* __restrict__ cols,
                                const float* __restrict__ vals,
                                int parity) {
    const float* src = parity ? g_cb : g_ca;
    float*       dst = parity ? g_ca : g_cb;
    int t = blockIdx.x * blockDim.x + threadIdx.x;
    if (t >= NNZ_PRE * 16) return;
    int e    = t >> 4;
    int lane = t & 15;
    int   r = __ldg(&rows[e]);
    int   c = __ldg(&cols[e]);
    float v = __ldg(&vals[e]);
    float4 x = ((const float4*)src)[c * 16 + lane];
    red_add_v4(&dst[r * 64 + lane * 4], v * x.x, v * x.y, v * x.z, v * x.w);
}

// process 4 edges: two broadcast int4 loads + 4 independent gathers
__device__ __forceinline__ void gather4(const int4* __restrict__ ellv,
                                        const float4* __restrict__ src4,
                                        int lane, float4& acc) {
    int4 p0 = ellv[0];   // edges i, i+1
    int4 p1 = ellv[1];   // edges i+2, i+3
    float v0 = __int_as_float(p0.y), v1 = __int_as_float(p0.w);
    float v2 = __int_as_float(p1.y), v3 = __int_as_float(p1.w);
    float4 x0 = src4[p0.x * 16 + lane];
    float4 x1 = src4[p0.z * 16 + lane];
    float4 x2 = src4[p1.x * 16 + lane];
    float4 x3 = src4[p1.z * 16 + lane];
    acc.x += v0 * x0.x + v1 * x1.x + v2 * x2.x + v3 * x3.x;
    acc.y += v0 * x0.y + v1 * x1.y + v2 * x2.y + v3 * x3.y;
    acc.z += v0 * x0.z + v1 * x1.z + v2 * x2.z + v3 * x3.z;
    acc.w += v0 * x0.w + v1 * x1.w + v2 * x2.w + v3 * x3.w;
}

// ---- fused layer: adj-SPMM (+ic for item rows) + perturb + accumulate ----
// mode: 0 = first layer (out = e), 1 = middle (out += e), 2 = last (out = (out+e)/3)
__global__ void __launch_bounds__(256)
layer_kernel(const float* __restrict__ ego_src,
             float* __restrict__ ego_dst,
             const float* __restrict__ cn,   // this layer's updated concepts
             const float* __restrict__ nk,
             float* __restrict__ out,
             int mode) {
    int t0   = blockIdx.x * blockDim.x + threadIdx.x;
    int lane = threadIdx.x & 15;
    const float4* src4 = (const float4*)ego_src;
    const float4* cn4  = (const float4*)cn;
    for (int t = t0; t < NTOT * 16; t += gridDim.x * blockDim.x) {
        int row  = t >> 4;
        int idx4 = row * 16 + lane;

        float4 acc = make_float4(0.f, 0.f, 0.f, 0.f);
        int n4 = (min(g_adj_cnt[row], CAP_ADJ) + 3) & ~3;
        const int4* ellv = (const int4*)&g_adj_ell[(size_t)row * CAP_ADJ];
        for (int i = 0; i < n4; i += 4, ellv += 2)
            gather4(ellv, src4, lane, acc);

        if (row >= USER_NUM) {
            int ir = row - USER_NUM;
            int m4 = (min(g_ic_cnt[ir], CAP_IC) + 3) & ~3;
            const int4* ellv2 = (const int4*)&g_ic_ell[(size_t)ir * CAP_IC];
            for (int i = 0; i < m4; i += 4, ellv2 += 2)
                gather4(ellv2, cn4, lane, acc);
        }

        // SimGCL perturbation: e += sign(e) * (nk/||nk||) * eps
        float4 nv = ((const float4*)nk)[idx4];
        float ss = nv.x * nv.x + nv.y * nv.y + nv.z * nv.z + nv.w * nv.w;
        ss += __shfl_xor_sync(0xffffffffu, ss, 1);
        ss += __shfl_xor_sync(0xffffffffu, ss, 2);
        ss += __shfl_xor_sync(0xffffffffu, ss, 4);
        ss += __shfl_xor_sync(0xffffffffu, ss, 8);
        float inv = EPS_F / fmaxf(sqrtf(ss), 1e-12f);

        acc.x += signf_(acc.x) * nv.x * inv;
        acc.y += signf_(acc.y) * nv.y * inv;
        acc.z += signf_(acc.z) * nv.z * inv;
        acc.w += signf_(acc.w) * nv.w * inv;

        ((float4*)ego_dst)[idx4] = acc;

        if (mode == 0) {
            ((float4*)out)[idx4] = acc;
        } else {
            float4 a = ((float4*)out)[idx4];
            a.x += acc.x; a.y += acc.y; a.z += acc.z; a.w += acc.w;
            if (mode == 2) {
                const float s = 1.f / (float)N_LAYERS;
                a.x *= s; a.y *= s; a.z *= s; a.w *= s;
            }
            ((float4*)out)[idx4] = a;
        }
    }
}

extern "C" void kernel_launch(void* const* d_in, const int* in_sizes, int n_in,
                              void* d_out, int out_size) {
    const float* user_emb    = (const float*)d_in[0];
    const float* item_emb    = (const float*)d_in[1];
    const float* concept_emb = (const float*)d_in[2];
    const int*   adj_rows    = (const int*)d_in[3];
    const int*   adj_cols    = (const int*)d_in[4];
    const float* adj_vals    = (const float*)d_in[5];
    const int*   pre_rows    = (const int*)d_in[6];
    const int*   pre_cols    = (const int*)d_in[7];
    const float* pre_vals    = (const float*)d_in[8];
    const int*   ic_rows     = (const int*)d_in[9];
    const int*   ic_cols     = (const int*)d_in[10];
    const float* ic_vals     = (const float*)d_in[11];
    const float* noise       = (const float*)d_in[12];
    float* out = (float*)d_out;

    const int TPB = 256;
    const int zc_blocks    = (NTOT + TPB - 1) / TPB;
    const int init_blocks  = (NTOT * EMB / 4 + TPB - 1) / TPB;
    const int badj_blocks  = (NNZ_ADJ + TPB - 1) / TPB;
    const int bic_blocks   = (NNZ_IC + TPB - 1) / TPB;
    const int pad_blocks   = (NTOT + ITEM_NUM + TPB - 1) / TPB;
    const int cc_blocks    = (CONCEPT_NUM * EMB / 4 + TPB - 1) / TPB;
    const int pre_blocks   = (NNZ_PRE * 16 + TPB - 1) / TPB;
    const int layer_blocks = (NTOT * 16 + TPB - 1) / TPB;

    zero_cnt_kernel<<<zc_blocks, TPB>>>();
    init_kernel<<<init_blocks, TPB>>>(user_emb, item_emb, concept_emb);
    build_adj_kernel<<<badj_blocks, TPB>>>(adj_rows, adj_cols, adj_vals);
    build_ic_kernel<<<bic_blocks, TPB>>>(ic_rows, ic_cols, ic_vals);
    pad_ell_kernel<<<pad_blocks, TPB>>>();

    float* ego_bufs[2];
    cudaGetSymbolAddress((void**)&ego_bufs[0], g_ego_a);
    cudaGetSymbolAddress((void**)&ego_bufs[1], g_ego_b);
    float* c_bufs[2];
    cudaGetSymbolAddress((void**)&c_bufs[0], g_ca);
    cudaGetSymbolAddress((void**)&c_bufs[1], g_cb);

    for (int k = 0; k < N_LAYERS; ++k) {
        int parity = k & 1;                    // concept dst: parity? g_ca : g_cb
        copy_c_kernel<<<cc_blocks, TPB>>>(parity);
        spmm_pre_kernel<<<pre_blocks, TPB>>>(pre_rows, pre_cols, pre_vals, parity);
        const float* cn = parity ? c_bufs[0] : c_bufs[1];
        const float* esrc = ego_bufs[k & 1];
        float*       edst = ego_bufs[(k + 1) & 1];
        int mode = (k == 0) ? 0 : (k == N_LAYERS - 1 ? 2 : 1);
        layer_kernel<<<layer_blocks, TPB>>>(esrc, edst, cn,
                                            noise + (size_t)k * NTOT * EMB,
                                            out, mode);
    }
}